// round 10
// baseline (speedup 1.0000x reference)
#include <cuda_runtime.h>
#include <cuda_bf16.h>
#include <cstdint>

#define LSEQ 2048
typedef unsigned long long ull;

__device__ float g_IZ[32 * LSEQ];
__device__ float g_ctx_scratch[2 * 16 * 2048 * 64];

// ---- score kernel smem (operand pitch 72 bf16 = 144B rows) ----
#define OKH 0
#define OKL 18432
#define OEH 36864
#define OEL 55296
#define ORS 73728
#define RSPITCH 260
#define SMEM_TOT (73728 + 128 * RSPITCH * 4)   // 206848

__device__ __forceinline__ uint32_t smem_u32(const void* p) {
    uint32_t a;
    asm("{ .reg .u64 t; cvta.to.shared.u64 t, %1; cvt.u32.u64 %0, t; }" : "=r"(a) : "l"(p));
    return a;
}
__device__ __forceinline__ void ldmA(uint32_t* a, uint32_t addr) {
    asm volatile("ldmatrix.sync.aligned.m8n8.x4.shared.b16 {%0,%1,%2,%3}, [%4];"
        : "=r"(a[0]), "=r"(a[1]), "=r"(a[2]), "=r"(a[3]) : "r"(addr));
}
__device__ __forceinline__ void ldmB(uint32_t* b, uint32_t addr) {
    asm volatile("ldmatrix.sync.aligned.m8n8.x2.shared.b16 {%0,%1}, [%2];"
        : "=r"(b[0]), "=r"(b[1]) : "r"(addr));
}
__device__ __forceinline__ void ldmBT(uint32_t* b, uint32_t addr) {
    asm volatile("ldmatrix.sync.aligned.m8n8.x2.trans.shared.b16 {%0,%1}, [%2];"
        : "=r"(b[0]), "=r"(b[1]) : "r"(addr));
}
__device__ __forceinline__ void mmabf(float* d, const uint32_t* a, const uint32_t* b) {
    asm volatile("mma.sync.aligned.m16n8k16.row.col.f32.bf16.bf16.f32 "
        "{%0,%1,%2,%3}, {%4,%5,%6,%7}, {%8,%9}, {%0,%1,%2,%3};"
        : "+f"(d[0]), "+f"(d[1]), "+f"(d[2]), "+f"(d[3])
        : "r"(a[0]), "r"(a[1]), "r"(a[2]), "r"(a[3]), "r"(b[0]), "r"(b[1]));
}
__device__ __forceinline__ uint32_t pkbf(float a, float b) {
    __nv_bfloat162 h = __floats2bfloat162_rn(a, b);
    return *(uint32_t*)&h;
}
__device__ __forceinline__ void split72(char* hi, char* lo, int r, int c4, float4 v) {
    float hx = __bfloat162float(__float2bfloat16(v.x));
    float hy = __bfloat162float(__float2bfloat16(v.y));
    float hz = __bfloat162float(__float2bfloat16(v.z));
    float hw = __bfloat162float(__float2bfloat16(v.w));
    int off = r * 144 + c4 * 8;
    *(uint2*)(hi + off) = make_uint2(pkbf(v.x, v.y), pkbf(v.z, v.w));
    *(uint2*)(lo + off) = make_uint2(pkbf(v.x - hx, v.y - hy), pkbf(v.z - hz, v.w - hw));
}

// ========== Kernel A: scores, incremental R ring + K/E prefetch ==========
__global__ void __launch_bounds__(256, 1)
score_mma(const float* __restrict__ Q, const float* __restrict__ K,
          const float* __restrict__ Er, float* __restrict__ attn)
{
    extern __shared__ char sm[];
    const uint32_t sb = smem_u32(sm);
    float* Rs = (float*)(sm + ORS);

    const int qt = 15 - (int)blockIdx.x;
    const int bh = blockIdx.y;
    const int q0 = qt * 128;
    const int t = threadIdx.x;
    const int wid = t >> 5, lane = t & 31;
    const int wm = wid >> 1, wn = wid & 1;

    const float* Qg = Q + (size_t)bh * LSEQ * 64;
    const float* Kg = K + (size_t)bh * LSEQ * 64;
    float* attng = attn + (size_t)bh * LSEQ * LSEQ;

    // stage Q in ring region (reused after fragments are in regs)
    for (int i = t; i < 2048; i += 256) {
        int r = i >> 4, c4 = i & 15;
        split72(sm + ORS, sm + ORS + 18432, r, c4,
                *((const float4*)(Qg + (size_t)(q0 + r) * 64 + 4 * c4)));
    }
    __syncthreads();

    const int arow = (lane & 7) + 8 * ((lane >> 3) & 1);
    const int acolB = 16 * (lane >> 4);
    uint32_t AH[2][4][4], AL[2][4][4];
#pragma unroll
    for (int mt = 0; mt < 2; mt++)
#pragma unroll
        for (int ks = 0; ks < 4; ks++) {
            uint32_t ro = (uint32_t)((32 * wm + 16 * mt + arow) * 144 + ks * 32 + acolB);
            ldmA(AH[mt][ks], sb + ORS + ro);
            ldmA(AL[mt][ks], sb + ORS + 18432 + ro);
        }

    const int browB = (lane & 7) * 144;
    const int bcolB = 16 * ((lane >> 3) & 1);
    float zacc[2][2] = {{0.f, 0.f}, {0.f, 0.f}};

    const int lr = t >> 4, lc4 = t & 15;

    // prefetch tile h=0
    float4 kb[8], eb[8];
    {
        const int k0 = qt * 128;
#pragma unroll
        for (int jj = 0; jj < 8; jj++)
            kb[jj] = *((const float4*)(Kg + (size_t)(k0 + lr + 16 * jj) * 64 + 4 * lc4));
#pragma unroll
        for (int jj = 0; jj < 8; jj++)
            eb[jj] = *((const float4*)(Er + (size_t)(2047 - (lr + 16 * jj)) * 64 + 4 * lc4));
    }

    for (int h = 0; h <= qt; h++) {
        const int k0 = (qt - h) * 128;
        __syncthreads();     // ring write-slot + K/E free

        // convert current prefetched K/E to smem
#pragma unroll
        for (int jj = 0; jj < 8; jj++)
            split72(sm + OKH, sm + OKL, lr + 16 * jj, lc4, kb[jj]);
#pragma unroll
        for (int jj = 0; jj < 8; jj++)
            split72(sm + OEH, sm + OEL, lr + 16 * jj, lc4, eb[jj]);

        // prefetch tile h+1 (overlaps with R/S MMA + epilogue below)
        if (h < qt) {
            const int k0n = (qt - h - 1) * 128;
            const int ebn = 2047 - 128 * (h + 1);
#pragma unroll
            for (int jj = 0; jj < 8; jj++)
                kb[jj] = *((const float4*)(Kg + (size_t)(k0n + lr + 16 * jj) * 64 + 4 * lc4));
#pragma unroll
            for (int jj = 0; jj < 8; jj++)
                eb[jj] = *((const float4*)(Er + (size_t)(ebn - (lr + 16 * jj)) * 64 + 4 * lc4));
        }
        __syncthreads();

        // ---- R phase: 128 new cols (block D_{h+1}) -> ring slot (h+1)&1 ----
        const int slotW = 128 * ((h + 1) & 1);
#pragma unroll 1
        for (int nt = 0; nt < 8; nt++) {
            float racc[2][4] = {{0.f, 0.f, 0.f, 0.f}, {0.f, 0.f, 0.f, 0.f}};
            const uint32_t nb = (uint32_t)((64 * wn + 8 * nt) * 144) + browB + bcolB;
#pragma unroll
            for (int ks = 0; ks < 4; ks++) {
                uint32_t BH[2], BL[2];
                ldmB(BH, sb + OEH + nb + ks * 32);
                ldmB(BL, sb + OEL + nb + ks * 32);
#pragma unroll
                for (int mt = 0; mt < 2; mt++) {
                    mmabf(racc[mt], AH[mt][ks], BH);
                    mmabf(racc[mt], AH[mt][ks], BL);
                    mmabf(racc[mt], AL[mt][ks], BH);
                }
            }
            const int c = slotW + 64 * wn + 8 * nt + 2 * (lane & 3);
#pragma unroll
            for (int mt = 0; mt < 2; mt++) {
                int q = 32 * wm + 16 * mt + (lane >> 2);
                *((float2*)(Rs + q * RSPITCH + c)) = make_float2(racc[mt][0], racc[mt][1]);
                *((float2*)(Rs + (q + 8) * RSPITCH + c)) = make_float2(racc[mt][2], racc[mt][3]);
            }
        }
        __syncthreads();     // ring visible

        // ---- S + epilogue over two 64-col halves ----
        const int sA = 128 * ((h + 1) & 1);
        const int sB = 128 * (h & 1);
        const bool diag = (h == 0);
#pragma unroll 1
        for (int kh = 0; kh < 2; kh++) {
            float sacc[2][4][4];
#pragma unroll
            for (int mt = 0; mt < 2; mt++)
#pragma unroll
                for (int nt = 0; nt < 4; nt++)
#pragma unroll
                    for (int r = 0; r < 4; r++) sacc[mt][nt][r] = 0.f;
#pragma unroll
            for (int nt = 0; nt < 4; nt++) {
                const uint32_t nb = (uint32_t)((64 * kh + 32 * wn + 8 * nt) * 144) + browB + bcolB;
#pragma unroll
                for (int ks = 0; ks < 4; ks++) {
                    uint32_t BH[2], BL[2];
                    ldmB(BH, sb + OKH + nb + ks * 32);
                    ldmB(BL, sb + OKL + nb + ks * 32);
#pragma unroll
                    for (int mt = 0; mt < 2; mt++) {
                        mmabf(sacc[mt][nt], AH[mt][ks], BH);
                        mmabf(sacc[mt][nt], AH[mt][ks], BL);
                        mmabf(sacc[mt][nt], AL[mt][ks], BH);
                    }
                }
            }
#pragma unroll
            for (int mt = 0; mt < 2; mt++) {
#pragma unroll
                for (int nt = 0; nt < 4; nt++) {
                    const int klocal = 64 * kh + 32 * wn + 8 * nt + 2 * (lane & 3);
                    const int kg = k0 + klocal;
#pragma unroll
                    for (int rh = 0; rh < 2; rh++) {
                        const int r = 32 * wm + 16 * mt + 8 * rh + (lane >> 2);
                        const int qg = q0 + r;
                        const int d0 = r - klocal;
                        const int d1 = d0 - 1;
                        float r0 = Rs[r * RSPITCH + ((d0 & 127) + (d0 >= 0 ? sA : sB))];
                        float r1 = Rs[r * RSPITCH + ((d1 & 127) + (d1 >= 0 ? sA : sB))];
                        float s0 = (sacc[mt][nt][2 * rh] + r0) * 0.125f;
                        float s1 = (sacc[mt][nt][2 * rh + 1] + r1) * 0.125f;
                        float p0 = __expf(s0), p1 = __expf(s1);
                        if (diag) {
                            if (kg > qg) p0 = 0.f;
                            if (kg + 1 > qg) p1 = 0.f;
                        }
                        zacc[mt][rh] += p0 + p1;
                        *((float2*)(attng + (size_t)qg * LSEQ + kg)) = make_float2(p0, p1);
                    }
                }
            }
        }
    }

    // ---- z reduce ----
#pragma unroll
    for (int mt = 0; mt < 2; mt++)
#pragma unroll
        for (int rh = 0; rh < 2; rh++) {
            float v = zacc[mt][rh];
            v += __shfl_xor_sync(0xffffffffu, v, 1);
            v += __shfl_xor_sync(0xffffffffu, v, 2);
            zacc[mt][rh] = v;
        }
    __syncthreads();
    float* zb = Rs;
    if ((lane & 3) == 0) {
#pragma unroll
        for (int mt = 0; mt < 2; mt++)
#pragma unroll
            for (int rh = 0; rh < 2; rh++) {
                int row = 32 * wm + 16 * mt + 8 * rh + (lane >> 2);
                zb[row * 2 + wn] = zacc[mt][rh];
            }
    }
    __syncthreads();
    if (t < 128)
        g_IZ[bh * LSEQ + q0 + t] = 1.f / (zb[2 * t] + zb[2 * t + 1]);
}

// ========== Kernel B: TC PV, direct P fragments, 3 CTAs/SM ==========
// smem: V hi [128][72bf16] | V lo | iz[128]
#define OVH 0
#define OVL 18432
#define OIZ 36864
#define SMEM_B_TOT 37440

__global__ void __launch_bounds__(256, 3)
pv_tc(const float* __restrict__ V, float* __restrict__ ctx, float* __restrict__ attn)
{
    extern __shared__ char sm[];
    const uint32_t sb = smem_u32(sm);
    float* smIZ = (float*)(sm + OIZ);
    if (ctx == nullptr) ctx = g_ctx_scratch;

    const int qt = 15 - (int)blockIdx.x;
    const int bh = blockIdx.y;
    const int q0 = qt * 128;
    const int t = threadIdx.x;
    const int wid = t >> 5, lane = t & 31;
    const int g = lane >> 2, tig = lane & 3;

    const float* Vg = V + (size_t)bh * LSEQ * 64;
    float* attng = attn + (size_t)bh * LSEQ * LSEQ;
    float* ctxg = ctx + (size_t)bh * LSEQ * 64;

    if (t < 128) smIZ[t] = g_IZ[bh * LSEQ + q0 + t];
    __syncthreads();

    // each warp owns exclusive q rows [16*wid, 16*wid+16)
    float iz0 = smIZ[16 * wid + g];
    float iz1 = smIZ[16 * wid + 8 + g];

    float cacc[8][4];
#pragma unroll
    for (int nt = 0; nt < 8; nt++)
#pragma unroll
        for (int r = 0; r < 4; r++) cacc[nt][r] = 0.f;

    const int btrow = (lane & 15) * 144;
    const int vr = t >> 4, vc4 = t & 15;

    for (int kt = 0; kt <= qt; kt++) {
        const int k0 = kt * 128;
        __syncthreads();                       // V smem free
        float4 vbuf[8];
#pragma unroll
        for (int jj = 0; jj < 8; jj++)
            vbuf[jj] = *((const float4*)(Vg + (size_t)(k0 + vr + 16 * jj) * 64 + 4 * vc4));
#pragma unroll
        for (int jj = 0; jj < 8; jj++)
            split72(sm + OVH, sm + OVL, vr + 16 * jj, vc4, vbuf[jj]);
        __syncthreads();                       // V visible

        float* rp0 = attng + (size_t)(q0 + 16 * wid + g) * LSEQ + k0 + 2 * tig;
        float* rp1 = attng + (size_t)(q0 + 16 * wid + 8 + g) * LSEQ + k0 + 2 * tig;

#pragma unroll 1
        for (int ks = 0; ks < 8; ks++) {
            // batched fragment loads (4 independent LDG.64)
            float2 p00 = *((const float2*)(rp0 + 16 * ks));
            float2 p10 = *((const float2*)(rp1 + 16 * ks));
            float2 p01 = *((const float2*)(rp0 + 16 * ks + 8));
            float2 p11 = *((const float2*)(rp1 + 16 * ks + 8));
            p00.x *= iz0; p00.y *= iz0; p01.x *= iz0; p01.y *= iz0;
            p10.x *= iz1; p10.y *= iz1; p11.x *= iz1; p11.y *= iz1;
            // write normalized attn (exclusive rows -> no race)
            *((float2*)(rp0 + 16 * ks))     = p00;
            *((float2*)(rp1 + 16 * ks))     = p10;
            *((float2*)(rp0 + 16 * ks + 8)) = p01;
            *((float2*)(rp1 + 16 * ks + 8)) = p11;
            // convert to hi/lo fragments
            uint32_t PH[4], PL[4];
            PH[0] = pkbf(p00.x, p00.y);
            PH[1] = pkbf(p10.x, p10.y);
            PH[2] = pkbf(p01.x, p01.y);
            PH[3] = pkbf(p11.x, p11.y);
            {
                float hx, hy;
                hx = __bfloat162float(__float2bfloat16(p00.x));
                hy = __bfloat162float(__float2bfloat16(p00.y));
                PL[0] = pkbf(p00.x - hx, p00.y - hy);
                hx = __bfloat162float(__float2bfloat16(p10.x));
                hy = __bfloat162float(__float2bfloat16(p10.y));
                PL[1] = pkbf(p10.x - hx, p10.y - hy);
                hx = __bfloat162float(__float2bfloat16(p01.x));
                hy = __bfloat162float(__float2bfloat16(p01.y));
                PL[2] = pkbf(p01.x - hx, p01.y - hy);
                hx = __bfloat162float(__float2bfloat16(p11.x));
                hy = __bfloat162float(__float2bfloat16(p11.y));
                PL[3] = pkbf(p11.x - hx, p11.y - hy);
            }
#pragma unroll
            for (int nt = 0; nt < 8; nt++) {
                uint32_t BH[2], BL[2];
                uint32_t bo = (uint32_t)(16 * ks * 144) + btrow + nt * 16;
                ldmBT(BH, sb + OVH + bo);
                ldmBT(BL, sb + OVL + bo);
                mmabf(cacc[nt], PH, BH);
                mmabf(cacc[nt], PH, BL);
                mmabf(cacc[nt], PL, BH);
            }
        }
    }

    // zero-fill future columns
    const int kend = (qt + 1) * 128;
    const int nz = (LSEQ - kend) >> 2;
    if (nz > 0) {
        const float4 z4 = make_float4(0.f, 0.f, 0.f, 0.f);
        for (int i = t; i < 128 * nz; i += 256) {
            int r = i / nz, c = i - r * nz;
            *((float4*)(attng + (size_t)(q0 + r) * LSEQ + kend + 4 * c)) = z4;
        }
    }

    // ctx epilogue
#pragma unroll
    for (int nt = 0; nt < 8; nt++)
#pragma unroll
        for (int rh = 0; rh < 2; rh++) {
            int q = q0 + 16 * wid + 8 * rh + g;
            int d = 8 * nt + 2 * tig;
            *((float2*)(ctxg + (size_t)q * 64 + d)) =
                make_float2(cacc[nt][2 * rh], cacc[nt][2 * rh + 1]);
        }
}

extern "C" void kernel_launch(void* const* d_in, const int* in_sizes, int n_in,
                              void* d_out, int out_size) {
    const float* Q  = (const float*)d_in[0];
    const float* K  = (const float*)d_in[1];
    const float* V  = (const float*)d_in[2];
    const float* Er = (const float*)d_in[4];

    const long long CTXN = (long long)2 * 16 * 2048 * 64;
    const long long ATTN = (long long)2 * 16 * 2048 * 2048;
    float* out = (float*)d_out;
    float* ctx; float* attn;
    if ((long long)out_size >= CTXN + ATTN) { ctx = out; attn = out + CTXN; }
    else if ((long long)out_size == ATTN)   { ctx = nullptr; attn = out; }
    else                                    { ctx = out; attn = out; }

    cudaFuncSetAttribute(score_mma, cudaFuncAttributeMaxDynamicSharedMemorySize, SMEM_TOT);
    score_mma<<<dim3(16, 32), 256, SMEM_TOT>>>(Q, K, Er, attn);

    cudaFuncSetAttribute(pv_tc, cudaFuncAttributeMaxDynamicSharedMemorySize, SMEM_B_TOT);
    pv_tc<<<dim3(16, 32), 256, SMEM_B_TOT>>>(V, ctx, attn);
}